// round 17
// baseline (speedup 1.0000x reference)
#include <cuda_runtime.h>

// SSIM loss, fused separable 11x11 gaussian blur + ssim map + mean reduce.
// R17 = R16 base (main 186us; NT=512, 4 CTAs, TH=22, INH=32) + 3 cuts:
//  (1) fields stored as one float4/pixel {Bs,Bs2,Bd,Bd2} -> P3 = 13 LDS.128
//      (one pointer) instead of 26 LDS.64 from two planes. Dense 16B stride,
//      conflict-free.
//  (2) P1 interior fast path (69% of blocks, uniform -> no divergence):
//      skips ~20 guard instrs/thread. Cols 74-75 loaded-but-unused by P2.
//  (3) reduce chain deleted: per-block atomicAdd into 32 spread slots
//      (hidden under main), fin sums in double + resets slots for replay.

#define IMG      512
#define TW       64
#define TH       22
#define HALO     5
#define INW      74          // TW + 2*HALO
#define INWP     76          // padded row stride
#define INH      32          // TH + 2*HALO
#define NT       512
#define QROW     256         // quad plane row: [64 cols][4 fields] floats

#define GX       8           // 512/64
#define GY       24          // 24*22 = 528 rows, tail masked
#define PL       96
#define ZC       48          // planes per main launch (2 launches)

#define SMEM_FLOATS (2 * INH * INWP + INH * QROW)   // 4864 + 8192 = 13056
#define SMEM_BYTES  (SMEM_FLOATS * 4)               // 52224

__device__ float g_acc[32];   // zero-init at load; fin resets after reading

// 1D gaussian, sigma=1.5, K=11, normalized. Constant indices fold to
// FFMA immediates (rt_SMSP=1 imm-form).
__device__ __forceinline__ constexpr float gw(int k) {
    switch (k) {
        case 0:  return 0.00102838f;
        case 1:  return 0.00759877f;
        case 2:  return 0.03600077f;
        case 3:  return 0.10936069f;
        case 4:  return 0.21300554f;
        case 5:  return 0.26601173f;
        case 6:  return 0.21300554f;
        case 7:  return 0.10936069f;
        case 8:  return 0.03600077f;
        case 9:  return 0.00759877f;
        case 10: return 0.00102838f;
    }
    return 0.0f;
}

// One half of the horizontal blur: 16-float window -> {B(x), B(x^2)} for
// 4 cols, stored into the quad plane at float offset `off` (0 for s-pair,
// 2 for d-pair): dst[row*QROW + 4*(c0+j) + off] = {f[j], f2[j]}.
__device__ __forceinline__ void hblur_half(const float* __restrict__ src,
                                           float* __restrict__ dst,
                                           int row, int c0, int off) {
    float a[16];
    {
        const float4* a4 = (const float4*)(src + row * INWP + c0);
        ((float4*)a)[0] = a4[0]; ((float4*)a)[1] = a4[1];
        ((float4*)a)[2] = a4[2]; ((float4*)a)[3] = a4[3];
    }
    float f[4]  = {0.f, 0.f, 0.f, 0.f};
    float f2[4] = {0.f, 0.f, 0.f, 0.f};
    #pragma unroll
    for (int i = 0; i < 14; i++) {
        float v = a[i];
        float vv = v * v;
        #pragma unroll
        for (int j = 0; j < 4; j++) {
            int k = i - j;
            if (k >= 0 && k < 11) {
                float w = gw(k);
                f[j]  = fmaf(v,  w, f[j]);
                f2[j] = fmaf(vv, w, f2[j]);
            }
        }
    }
    float* h = dst + row * QROW + 4 * c0 + off;
    #pragma unroll
    for (int j = 0; j < 4; j++)
        *(float2*)(h + 4 * j) = make_float2(f[j], f2[j]);
}

__global__ __launch_bounds__(NT, 4)
void ssim_main(const float* __restrict__ img1, const float* __restrict__ img2,
               int z0) {
    extern __shared__ float smem[];
    float* ss = smem;                       // s = x1+x2 tile [INH][INWP]
    float* sd = smem + INH * INWP;          // d = x1-x2 tile
    float* sq = smem + 2 * INH * INWP;      // quad plane [INH][64][4]
    __shared__ float wsum[NT / 32];

    const int tid = threadIdx.x;
    const int gx0 = blockIdx.x * TW - HALO;
    const int gy0 = blockIdx.y * TH - HALO;
    const size_t pbase = (size_t)(blockIdx.z + z0) * (IMG * IMG);
    const float* p1 = img1 + pbase;
    const float* p2 = img2 + pbase;

    // ---- Phase 1: global -> smem. s=(i1+i2)*0.5+1, d=(i1-i2)*0.5. ----
    {
        const int r  = tid >> 4;
        const int c  = tid & 15;
        const int gy = gy0 + r;
        const float* q1 = p1 + (ptrdiff_t)gy * IMG;
        const float* q2 = p2 + (ptrdiff_t)gy * IMG;
        const bool interior = (gx0 >= 0) && (gx0 + INW <= IMG) &&
                              (gy0 >= 0) && (gy0 + INH <= IMG);
        if (interior) {
            // no per-element guards; cols 74,75 are stored but unused by P2
            #pragma unroll
            for (int k = 0; k < 5; k++) {
                int cc = c + 16 * k;
                if (k < 4 || cc < INWP) {
                    float a = q1[gx0 + cc], b = q2[gx0 + cc];
                    ss[r * INWP + cc] = fmaf(a + b, 0.5f, 1.0f);
                    sd[r * INWP + cc] = (a - b) * 0.5f;
                }
            }
        } else {
            const bool rowok = (gy >= 0) && (gy < IMG);
            #pragma unroll
            for (int k = 0; k < 5; k++) {
                int cc = c + 16 * k;
                if (k < 4 || cc < INWP) {
                    int gx = gx0 + cc;
                    float vs = 0.f, vd = 0.f;
                    if (rowok && cc < INW && gx >= 0 && gx < IMG) {
                        float a = q1[gx], b = q2[gx];
                        vs = fmaf(a + b, 0.5f, 1.0f);
                        vd = (a - b) * 0.5f;
                    }
                    ss[r * INWP + cc] = vs;
                    sd[r * INWP + cc] = vd;
                }
            }
        }
    }
    __syncthreads();

    // ---- Phase 2: horizontal blur, 4 output cols/thread, 512 tasks ----
    {
        const int row = tid >> 4;           // 0..31
        const int c0  = (tid & 15) << 2;    // 0,4,...,60
        hblur_half(ss, sq, row, c0, 0);     // s half -> {Bs,Bs2}
        hblur_half(sd, sq, row, c0, 2);     // d half -> {Bd,Bd2}
    }
    __syncthreads();

    // ---- Phase 3: vertical blur + ssim. 64 cols x 8 groups
    //      (rows 3,3,3,3,3,3,2,2), one LDS.128 per tap ----
    const int col = tid & 63;
    const int g   = tid >> 6;               // 0..7
    const int r_start = (g < 6) ? 3 * g : 18 + 2 * (g - 6);
    const int nrows   = (g < 6) ? 3 : 2;

    float aS[3], aS2[3], aD[3], aD2[3];
    #pragma unroll
    for (int j = 0; j < 3; j++) {
        aS[j] = 0.f; aS2[j] = 0.f; aD[j] = 0.f; aD2[j] = 0.f;
    }

    #pragma unroll
    for (int i = 0; i < 13; i++) {
        int ri = r_start + i;
        if (ri > INH - 1) ri = INH - 1;      // clamp feeds only masked outputs
        float4 h = *(const float4*)(sq + ri * QROW + 4 * col);
        #pragma unroll
        for (int j = 0; j < 3; j++) {
            int k = i - j;
            if (k >= 0 && k < 11) {
                float w = gw(k);
                aS[j]  = fmaf(h.x, w, aS[j]);
                aS2[j] = fmaf(h.y, w, aS2[j]);
                aD[j]  = fmaf(h.z, w, aD[j]);
                aD2[j] = fmaf(h.w, w, aD2[j]);
            }
        }
    }

    const float C1 = 0.0001f;   // 0.01^2
    const float C2 = 0.0009f;   // 0.03^2
    const int   gyb = blockIdx.y * TH + r_start;
    float tsum = 0.f;
    #pragma unroll
    for (int j = 0; j < 3; j++) {
        bool valid = (j < nrows) && (gyb + j < IMG);
        if (valid) {
            float Bs  = aS[j],  Bd  = aD[j];
            float Bs2 = aS2[j], Bd2 = aD2[j];
            float bss = Bs * Bs, bdd = Bd * Bd;
            float mu12   = 0.25f * (bss - bdd);        // mu1*mu2
            float musq   = 0.50f * (bss + bdd);        // mu1^2 + mu2^2
            float sig12  = 0.25f * (Bs2 - Bd2) - mu12; // sigma12
            float sigsum = 0.50f * (Bs2 + Bd2) - musq; // sig1^2 + sig2^2
            float num = fmaf(2.f, mu12,  C1) * fmaf(2.f, sig12, C2);
            float den = (musq + C1) * (sigsum + C2);
            tsum += __fdividef(num, den);
        }
    }

    // ---- Reduction: warp shuffle -> wsum (1 barrier) -> spread atomic ----
    #pragma unroll
    for (int off = 16; off; off >>= 1)
        tsum += __shfl_xor_sync(0xffffffffu, tsum, off);

    if ((tid & 31) == 0) wsum[tid >> 5] = tsum;
    __syncthreads();
    if (tid == 0) {
        float bs = 0.f;
        #pragma unroll
        for (int i = 0; i < NT / 32; i++) bs += wsum[i];
        int slot = (blockIdx.x + blockIdx.y + (blockIdx.z + z0) * 3) & 31;
        atomicAdd(&g_acc[slot], bs);
    }
}

__global__ void ssim_fin(float* out, double inv_n) {
    const int tid = threadIdx.x;   // 32 threads
    double s = (double)g_acc[tid];
    #pragma unroll
    for (int off = 16; off; off >>= 1)
        s += __shfl_xor_sync(0xffffffffu, s, off);
    if (tid == 0) out[0] = 1.0f - (float)(s * inv_n);
    g_acc[tid] = 0.f;              // reset for the next graph replay
}

extern "C" void kernel_launch(void* const* d_in, const int* in_sizes, int n_in,
                              void* d_out, int out_size) {
    const float* img1 = (const float*)d_in[0];
    const float* img2 = (const float*)d_in[1];
    (void)n_in; (void)out_size; (void)in_sizes;

    cudaFuncSetAttribute(ssim_main, cudaFuncAttributeMaxDynamicSharedMemorySize,
                         SMEM_BYTES);

    dim3 grid(GX, GY, ZC);
    ssim_main<<<grid, NT, SMEM_BYTES>>>(img1, img2, 0);
    ssim_main<<<grid, NT, SMEM_BYTES>>>(img1, img2, ZC);

    double inv_n = 1.0 / ((double)PL * IMG * IMG);
    ssim_fin<<<1, 32>>>((float*)d_out, inv_n);
}